// round 7
// baseline (speedup 1.0000x reference)
#include <cuda_runtime.h>
#include <cstdint>
#include <cstddef>

// RWW whole-brain sim, 8-CTA cluster, Con_Mtx register-resident.
// R7: pipelined exchange. Per-source mbarriers [buf][src] (expect_tx=256,
//     fed by two 128B half-copies). Warps 0-7 / 8-15 sync on separate named
//     barriers; each half's copies launch immediately (7 lanes issue 7
//     destinations in parallel). No self-copy: a thread's 64 columns come
//     from exactly one source CTA q, and q==cta threads read the local
//     staging buffer (offset by cta*16 B to keep LDS conflict-free).

#define NREG    512
#define NSTEPS  20000
#define NCTAS   8
#define NTHR    512

#define EF 68                         // stripe stride in floats (272 B)
#define PF 544                        // floats per x parity buffer
#define XB      (2 * PF * 4)          // 4352 B : x buffers
#define STG     XB                    // staging: + cta*16 + b*256 (<= 4976)
#define MB_OFF  5120                  // 16 mbarriers * 8 B
#define SMEM_BYTES 5376

__device__ __forceinline__ unsigned long long ffma2(
    unsigned long long a, unsigned long long b, unsigned long long c) {
    unsigned long long d;
    asm("fma.rn.f32x2 %0, %1, %2, %3;" : "=l"(d) : "l"(a), "l"(b), "l"(c));
    return d;
}
__device__ __forceinline__ float fsum2(unsigned long long a) {
    float2 f = *reinterpret_cast<float2*>(&a);
    return f.x + f.y;
}
__device__ __forceinline__ void mbar_wait(uint32_t mb, uint32_t par) {
    asm volatile(
        "{\n\t"
        ".reg .pred P;\n"
        "WL_%=:\n\t"
        "mbarrier.try_wait.parity.acquire.cluster.shared::cta.b64 P, [%0], %1, 0x989680;\n\t"
        "@!P bra WL_%=;\n\t"
        "}" :: "r"(mb), "r"(par) : "memory");
}

__device__ __forceinline__ float Hfun(float I, float a, float b, float d, float bigc) {
    float x     = fmaf(a, I, -b);
    float numer = fabsf(x) + 1e-9f;
    float neg   = -d * x;
    float e     = __expf(fminf(neg, 51.0f));
    float den_s = fabsf(1.0f - e) + 1e-9f * d;
    float den_b = fabsf(1.0f - bigc * neg) + 1e-9f * d;
    float denom = (neg > 50.0f) ? den_b : den_s;
    return __fdividef(numer, denom);
}

extern __shared__ float smx[];

__global__ void __launch_bounds__(NTHR, 1) __cluster_dims__(NCTAS, 1, 1)
rww_kernel(const float* __restrict__ init_state,   // (512, 2)
           const float* __restrict__ Con,          // (512, 512) row-major
           const float* __restrict__ vofT,         // (20000, 512)
           float* __restrict__ out)                // 1024 final + 20000*1024 hist
{
    const int tid  = (int)threadIdx.x;
    const int cta  = (int)blockIdx.x;          // cluster rank
    const int lane = tid & 31;
    const int wrp  = tid >> 5;                 // warp 0..15
    const int r    = tid >> 3;                 // local row 0..63
    const int q    = tid & 7;                  // column eighth == source CTA
    const int j    = cta * 64 + r;             // global region of this row

    uint32_t sb;
    asm("{ .reg .u64 t; cvta.to.shared.u64 t, %1; cvt.u32.u64 %0, t; }"
        : "=r"(sb) : "l"(smx));

    // ---- 16 mbarriers [buf][src]: count=1, phase-0 armed expect_tx=256 ----
    if (tid < 16) {
        uint32_t mb = sb + MB_OFF + (uint32_t)(tid * 8);
        asm volatile("mbarrier.init.shared.b64 [%0], %1;" :: "r"(mb), "r"(1));
        asm volatile("mbarrier.arrive.expect_tx.shared.b64 _, [%0], %1;"
                     :: "r"(mb), "r"(256) : "memory");
    }

    // ---- Con row segment: cols q*64..q*64+63 -> 32 packed f32x2 regs ----
    unsigned long long c64[32];
    {
        const ulonglong2* src =
            (const ulonglong2*)(Con + (size_t)j * NREG + (size_t)q * 64);
        #pragma unroll
        for (int it = 0; it < 16; ++it) {
            ulonglong2 t2 = src[it];
            c64[2*it] = t2.x; c64[2*it+1] = t2.y;
        }
    }

    // ---- init: x buffer 0 (all stripes) + staging buffer 1 (local stripe) ----
    if (tid < NREG)
        smx[(tid >> 6) * EF + (tid & 63)] = init_state[2 * tid];

    float sE = init_state[2 * j];
    float sI = init_state[2 * j + 1];
    if (q == 0)
        smx[STG / 4 + cta * 4 + 64 + r] = sE;   // stg[b=1][r] for t=0 local reads

    // peer smem bases (rank-preserving offsets)
    uint32_t remBase[NCTAS];
    #pragma unroll
    for (int d = 0; d < NCTAS; ++d)
        asm("mapa.shared::cluster.u32 %0, %1, %2;" : "=r"(remBase[d]) : "r"(sb), "r"(d));

    __syncthreads();
    asm volatile("barrier.cluster.arrive.aligned;" ::: "memory");
    asm volatile("barrier.cluster.wait.aligned;"   ::: "memory");

    float vc = __ldg(vofT + j);
    float vn = __ldg(vofT + NREG + j);
    float2* outv = (float2*)out;

    int ph0 = 0, ph1 = 0;                 // phase of my source barrier, per buf
    const bool isLocal = (q == cta);
    const bool sendwarp = (wrp == 0) || (wrp == 8);

    for (int t = 0; t < NSTEPS; ++t) {
        const int b = t & 1;

        // ---- wait only for MY source's data (local source: no wait) ----
        if (t) {
            if (!isLocal) {
                uint32_t mb = sb + MB_OFF + (uint32_t)(((b << 3) + q) * 8);
                mbar_wait(mb, (uint32_t)(b ? ph1 : ph0));
                if (tid == q)   // one thread per source re-arms next phase
                    asm volatile("mbarrier.arrive.expect_tx.shared.b64 _, [%0], %1;"
                                 :: "r"(mb), "r"(256) : "memory");
            }
            if (b) ph1 ^= 1; else ph0 ^= 1;
        }

        // ---- matvec: 64 cols from source q (x stripe or local staging) ----
        const ulonglong2* x2 = isLocal
            ? (const ulonglong2*)((const char*)smx + STG + cta * 16 + (b ^ 1) * 256)
            : (const ulonglong2*)((const char*)smx + (b ? PF * 4 : 0) + q * (EF * 4));
        unsigned long long a0 = 0ULL, a1 = 0ULL, a2 = 0ULL, a3 = 0ULL;
        #pragma unroll
        for (int it = 0; it < 8; ++it) {
            ulonglong2 xa = x2[2*it];
            ulonglong2 xb = x2[2*it+1];
            a0 = ffma2(c64[4*it+0], xa.x, a0);
            a1 = ffma2(c64[4*it+1], xa.y, a1);
            a2 = ffma2(c64[4*it+2], xb.x, a2);
            a3 = ffma2(c64[4*it+3], xb.y, a3);
        }
        float acc = (fsum2(a0) + fsum2(a1)) + (fsum2(a2) + fsum2(a3));
        acc += __shfl_xor_sync(0xffffffffu, acc, 1);
        acc += __shfl_xor_sync(0xffffffffu, acc, 2);
        acc += __shfl_xor_sync(0xffffffffu, acc, 4);

        // ---- epilogue (replicated across the 8 lanes of the row) ----
        float I_E = 0.382f  + 0.21f * sE + 3.0f * acc - sI;   // LAMBDA=0 folded
        float I_I = 0.2674f + 0.15f * sE - sI;
        float rE = Hfun(I_E, 310.0f, 125.0f, 0.16f,  1e9f);
        float rI = Hfun(I_I, 615.0f, 177.0f, 0.087f, 1e5f);
        float dE = -sE * 0.01f + (1.0f - sE) * 6.41e-4f * rE + 0.01f * vc;
        float dI = -sI * 0.1f  + 1.0e-3f * rI + 0.01f * vc;
        sE = fmaf(1e-4f, dE, sE);
        sI = fmaf(1e-4f, dI, sI);

        // ---- stage this CTA's new S_E (double-buffered, cta-shifted) ----
        if (q == 0) {
            smx[STG / 4 + cta * 4 + b * 64 + r] = sE;
            outv[512 + (size_t)t * NREG + j] = make_float2(sE, sI);
        }

        // ---- half barriers: rows 0-31 (warps 0-7) / rows 32-63 (8-15) ----
        if (wrp < 8) asm volatile("bar.sync 1, 256;" ::: "memory");
        else         asm volatile("bar.sync 2, 256;" ::: "memory");

        // ---- each half: 7 lanes ship 7 parallel 128B copies + tx ----
        if (sendwarp && lane < 8 && lane != cta && (t + 1 < NSTEPS)) {
            const int H = (wrp == 8);
            asm volatile("fence.proxy.async.shared::cta;" ::: "memory");
            uint32_t src = sb + (uint32_t)(STG + cta * 16 + b * 256 + H * 128);
            uint32_t dst = remBase[lane] +
                           (uint32_t)((b ? 0 : PF * 4) + cta * (EF * 4) + H * 128);
            uint32_t rmb = remBase[lane] +
                           (uint32_t)(MB_OFF + ((((b ^ 1) << 3) + cta) * 8));
            asm volatile(
                "cp.async.bulk.shared::cluster.shared::cta.mbarrier::complete_tx::bytes "
                "[%0], [%1], %2, [%3];"
                :: "r"(dst), "r"(src), "r"(128), "r"(rmb) : "memory");
        }

        // noise prefetch t+2 (off critical path)
        int t2 = t + 2; if (t2 >= NSTEPS) t2 = NSTEPS - 1;
        float vf = __ldg(vofT + (size_t)t2 * NREG + j);
        vc = vn; vn = vf;
    }

    if (q == 0) outv[j] = make_float2(sE, sI);

    asm volatile("barrier.cluster.arrive.aligned;" ::: "memory");
    asm volatile("barrier.cluster.wait.aligned;"   ::: "memory");
}

extern "C" void kernel_launch(void* const* d_in, const int* in_sizes, int n_in,
                              void* d_out, int out_size) {
    const float* init = nullptr;
    const float* con  = nullptr;
    const float* v    = nullptr;
    for (int i = 0; i < n_in; ++i) {
        if      (in_sizes[i] == NREG * 2)      init = (const float*)d_in[i];
        else if (in_sizes[i] == NREG * NREG)   con  = (const float*)d_in[i];
        else if (in_sizes[i] == NSTEPS * NREG) v    = (const float*)d_in[i];
    }
    rww_kernel<<<NCTAS, NTHR, SMEM_BYTES>>>(init, con, v, (float*)d_out);
    (void)out_size;
}

// round 8
// speedup vs baseline: 1.2896x; 1.2896x over previous
#include <cuda_runtime.h>
#include <cstdint>
#include <cstddef>

// RWW whole-brain sim, 8-CTA cluster, Con_Mtx register-resident.
// R8 = R6 exchange (8x256B bulk copies + 2 tx-mbarriers, the proven scheme)
//      with the critical path thinned:
//   - no shuffle reduce: threads STS 64-col partial sums to smem
//   - epilogue/state/history/noise on 64 threads (warps 0-1) only;
//     warps 2-15 go straight to the next try_wait (HW sleep)
//   - copies issued by 8 lanes in parallel after a 64-thread named barrier

#define NREG    512
#define NSTEPS  20000
#define NCTAS   8
#define NTHR    512

#define EF 68                          // x stripe stride in floats (272 B)
#define PF 544                         // floats per x parity buffer
#define XB       (2 * PF * 4)          // 4352 B x buffers
#define SUM_OFF  4352                  // 512 partial sums (2048 B)
#define STG_OFF  6400                  // 2 x 256 B staging
#define MB_OFF   6912                  // 2 mbarriers
#define SMEM_BYTES 7168

__device__ __forceinline__ unsigned long long ffma2(
    unsigned long long a, unsigned long long b, unsigned long long c) {
    unsigned long long d;
    asm("fma.rn.f32x2 %0, %1, %2, %3;" : "=l"(d) : "l"(a), "l"(b), "l"(c));
    return d;
}
__device__ __forceinline__ float fsum2(unsigned long long a) {
    float2 f = *reinterpret_cast<float2*>(&a);
    return f.x + f.y;
}
__device__ __forceinline__ void mbar_wait(uint32_t mb, uint32_t par) {
    asm volatile(
        "{\n\t"
        ".reg .pred P;\n"
        "WL_%=:\n\t"
        "mbarrier.try_wait.parity.acquire.cluster.shared::cta.b64 P, [%0], %1, 0x989680;\n\t"
        "@!P bra WL_%=;\n\t"
        "}" :: "r"(mb), "r"(par) : "memory");
}

__device__ __forceinline__ float Hfun(float I, float a, float b, float d, float bigc) {
    float x     = fmaf(a, I, -b);
    float numer = fabsf(x) + 1e-9f;
    float neg   = -d * x;
    float e     = __expf(fminf(neg, 51.0f));
    float den_s = fabsf(1.0f - e) + 1e-9f * d;
    float den_b = fabsf(1.0f - bigc * neg) + 1e-9f * d;
    float denom = (neg > 50.0f) ? den_b : den_s;
    return __fdividef(numer, denom);
}

extern __shared__ float smx[];

__global__ void __launch_bounds__(NTHR, 1) __cluster_dims__(NCTAS, 1, 1)
rww_kernel(const float* __restrict__ init_state,   // (512, 2)
           const float* __restrict__ Con,          // (512, 512) row-major
           const float* __restrict__ vofT,         // (20000, 512)
           float* __restrict__ out)                // 1024 final + 20000*1024 hist
{
    const int tid  = (int)threadIdx.x;
    const int cta  = (int)blockIdx.x;          // cluster rank
    const int r    = tid >> 3;                 // local row 0..63
    const int q    = tid & 7;                  // column eighth 0..7
    const int j    = cta * 64 + r;             // global region of this row

    uint32_t sb;
    asm("{ .reg .u64 t; cvta.to.shared.u64 t, %1; cvt.u32.u64 %0, t; }"
        : "=r"(sb) : "l"(smx));
    const uint32_t mb0 = sb + MB_OFF;
    const uint32_t mb1 = sb + MB_OFF + 8;

    if (tid == 0) {
        asm volatile("mbarrier.init.shared.b64 [%0], %1;" :: "r"(mb0), "r"(1));
        asm volatile("mbarrier.init.shared.b64 [%0], %1;" :: "r"(mb1), "r"(1));
        asm volatile("mbarrier.arrive.expect_tx.shared.b64 _, [%0], %1;"
                     :: "r"(mb0), "r"(2048) : "memory");
        asm volatile("mbarrier.arrive.expect_tx.shared.b64 _, [%0], %1;"
                     :: "r"(mb1), "r"(2048) : "memory");
    }

    // ---- Con row segment: cols q*64..q*64+63 -> 32 packed f32x2 regs ----
    unsigned long long c64[32];
    {
        const ulonglong2* src =
            (const ulonglong2*)(Con + (size_t)j * NREG + (size_t)q * 64);
        #pragma unroll
        for (int it = 0; it < 16; ++it) {
            ulonglong2 t2 = src[it];
            c64[2*it] = t2.x; c64[2*it+1] = t2.y;
        }
    }

    // ---- init x buffer 0 locally: x[k] @ (k>>6)*EF + (k&63) ----
    if (tid < NREG)
        smx[(tid >> 6) * EF + (tid & 63)] = init_state[2 * tid];

    // ---- per-region state: ONLY threads 0..63 (row = tid) ----
    float sE = 0.0f, sI = 0.0f;
    if (tid < 64) {
        sE = init_state[2 * (cta * 64 + tid)];
        sI = init_state[2 * (cta * 64 + tid) + 1];
    }

    // peer smem bases (rank-preserving offsets); used by lanes 0..7 of warp 0
    uint32_t remBase[NCTAS];
    #pragma unroll
    for (int d = 0; d < NCTAS; ++d)
        asm("mapa.shared::cluster.u32 %0, %1, %2;" : "=r"(remBase[d]) : "r"(sb), "r"(d));

    __syncthreads();
    asm volatile("barrier.cluster.arrive.aligned;" ::: "memory");
    asm volatile("barrier.cluster.wait.aligned;"   ::: "memory");

    // noise pipeline (threads 0..63 only), 2 deep
    float vc = 0.0f, vn = 0.0f;
    if (tid < 64) {
        vc = __ldg(vofT + cta * 64 + tid);
        vn = __ldg(vofT + NREG + cta * 64 + tid);
    }
    float2* outv = (float2*)out;

    int ph0 = 0, ph1 = 0;

    for (int t = 0; t < NSTEPS; ++t) {
        const int b = t & 1;

        // ---- wait for this step's x data (skip t=0: local init) ----
        if (t) {
            const uint32_t mb = b ? mb1 : mb0;
            mbar_wait(mb, (uint32_t)(b ? ph1 : ph0));
            if (b) ph1 ^= 1; else ph0 ^= 1;
            if (tid == 0)
                asm volatile("mbarrier.arrive.expect_tx.shared.b64 _, [%0], %1;"
                             :: "r"(mb), "r"(2048) : "memory");
        }

        // early noise prefetch for t+2 (epilogue threads only)
        float vf = 0.0f;
        if (tid < 64) {
            int t2 = t + 2; if (t2 >= NSTEPS) t2 = NSTEPS - 1;
            vf = __ldg(vofT + (size_t)t2 * NREG + cta * 64 + tid);
        }

        // ---- matvec: 64 cols/thread -> one partial sum, STS to smem ----
        const ulonglong2* x2 = (const ulonglong2*)
            ((const char*)smx + (b ? PF * 4 : 0) + q * (EF * 4));
        unsigned long long a0 = 0ULL, a1 = 0ULL, a2 = 0ULL, a3 = 0ULL;
        #pragma unroll
        for (int it = 0; it < 8; ++it) {
            ulonglong2 xa = x2[2*it];
            ulonglong2 xb = x2[2*it+1];
            a0 = ffma2(c64[4*it+0], xa.x, a0);
            a1 = ffma2(c64[4*it+1], xa.y, a1);
            a2 = ffma2(c64[4*it+2], xb.x, a2);
            a3 = ffma2(c64[4*it+3], xb.y, a3);
        }
        smx[SUM_OFF / 4 + tid] =
            (fsum2(a0) + fsum2(a1)) + (fsum2(a2) + fsum2(a3));

        __syncthreads();   // partials visible; warps 2-15 sprint to next wait

        if (tid < 64) {
            // ---- reduce 8 partials for my row ----
            const float4* sp = (const float4*)(smx + SUM_OFF / 4 + tid * 8);
            float4 s0 = sp[0], s1 = sp[1];
            float acc = ((s0.x + s0.y) + (s0.z + s0.w))
                      + ((s1.x + s1.y) + (s1.z + s1.w));

            // ---- epilogue (one thread per row) ----
            float I_E = 0.382f  + 0.21f * sE + 3.0f * acc - sI;  // LAMBDA=0
            float I_I = 0.2674f + 0.15f * sE - sI;
            float rE = Hfun(I_E, 310.0f, 125.0f, 0.16f,  1e9f);
            float rI = Hfun(I_I, 615.0f, 177.0f, 0.087f, 1e5f);
            float dE = -sE * 0.01f + (1.0f - sE) * 6.41e-4f * rE + 0.01f * vc;
            float dI = -sI * 0.1f  + 1.0e-3f * rI + 0.01f * vc;
            sE = fmaf(1e-4f, dE, sE);
            sI = fmaf(1e-4f, dI, sI);

            // stage new S_E (double-buffered) + history
            smx[STG_OFF / 4 + b * 64 + tid] = sE;
            outv[512 + (size_t)t * NREG + cta * 64 + tid] = make_float2(sE, sI);

            // 64-thread barrier: staging complete
            asm volatile("bar.sync 1, 64;" ::: "memory");

            // ---- 8 lanes ship 8 parallel 256B copies (data+tx fused) ----
            if (tid < 8 && (t + 1 < NSTEPS)) {
                asm volatile("fence.proxy.async.shared::cta;" ::: "memory");
                uint32_t src  = sb + (uint32_t)(STG_OFF + b * 256);
                uint32_t dst  = remBase[tid] +
                                (uint32_t)((b ? 0 : PF * 4) + cta * (EF * 4));
                uint32_t rmb  = remBase[tid] +
                                (uint32_t)(MB_OFF + ((b ^ 1) ? 8 : 0));
                asm volatile(
                    "cp.async.bulk.shared::cluster.shared::cta.mbarrier::complete_tx::bytes "
                    "[%0], [%1], %2, [%3];"
                    :: "r"(dst), "r"(src), "r"(256), "r"(rmb) : "memory");
            }

            vc = vn; vn = vf;
        }
    }

    if (tid < 64) outv[cta * 64 + tid] = make_float2(sE, sI);

    asm volatile("barrier.cluster.arrive.aligned;" ::: "memory");
    asm volatile("barrier.cluster.wait.aligned;"   ::: "memory");
}

extern "C" void kernel_launch(void* const* d_in, const int* in_sizes, int n_in,
                              void* d_out, int out_size) {
    const float* init = nullptr;
    const float* con  = nullptr;
    const float* v    = nullptr;
    for (int i = 0; i < n_in; ++i) {
        if      (in_sizes[i] == NREG * 2)      init = (const float*)d_in[i];
        else if (in_sizes[i] == NREG * NREG)   con  = (const float*)d_in[i];
        else if (in_sizes[i] == NSTEPS * NREG) v    = (const float*)d_in[i];
    }
    rww_kernel<<<NCTAS, NTHR, SMEM_BYTES>>>(init, con, v, (float*)d_out);
    (void)out_size;
}